// round 1
// baseline (speedup 1.0000x reference)
#include <cuda_runtime.h>
#include <cuda_bf16.h>

#define BB  2048
#define TT  500
#define NIN 64
#define BT  (BB*TT)

// Scratch (allocation-free rule: device globals).
__device__ float g_S[TT*BB];                  // [t][b] raw input sums (4 MB, L2-resident)
__device__ float g_R[(size_t)TT*BB*12];       // [t][b][12] per-step outputs, t-major (coalesced stores)

// ---------------------------------------------------------------------------
// K1: per-(b,t) sum over N=64 inputs. 16 threads/row, float4 loads,
// shuffle-tree reduce, smem gather so g_S writes are coalesced in b.
// grid (BB/32, TT), block 512 (= 32 rows x 16 lanes).
// ---------------------------------------------------------------------------
__global__ void __launch_bounds__(512) reduce_kernel(const float* __restrict__ in) {
    __shared__ float s_sum[32];
    int tid   = threadIdx.x;
    int rowid = tid >> 4;
    int sub   = tid & 15;
    int b     = blockIdx.x * 32 + rowid;
    int t     = blockIdx.y;

    const float4* p = (const float4*)(in + ((size_t)b * TT + t) * NIN);
    float4 v = p[sub];
    float s = (v.x + v.y) + (v.z + v.w);
    s += __shfl_down_sync(0xFFFFFFFFu, s, 8);
    s += __shfl_down_sync(0xFFFFFFFFu, s, 4);
    s += __shfl_down_sync(0xFFFFFFFFu, s, 2);
    s += __shfl_down_sync(0xFFFFFFFFu, s, 1);
    if (sub == 0) s_sum[rowid] = s;
    __syncthreads();
    if (tid < 32) g_S[t * BB + blockIdx.x * 32 + tid] = s_sum[tid];
}

// ---------------------------------------------------------------------------
// K2: the sequential scan. One thread = one (batch, channel) pair;
// the two channels run the same code with per-lane weights, so the warp
// stays convergent. 128 blocks x 32 threads = 128 warps on 128 SMs.
// ---------------------------------------------------------------------------
__device__ __forceinline__ void izh(float& v, float& u, float& z, float I,
                                    float a, float bb, float c, float d) {
    float vn = v + 0.25f * (0.04f * v * v + 5.0f * v + 140.0f - u + I);
    float un = u + (0.25f * a) * (bb * v - u);
    bool sp = (vn >= 30.0f);
    z = sp ? 1.0f : 0.0f;
    v = sp ? c : vn;
    u = sp ? (un + d) : un;
}

__global__ void __launch_bounds__(32, 1) scan_kernel(const float* __restrict__ W) {
    int lane = threadIdx.x;
    int ch   = lane & 1;
    int b    = blockIdx.x * 16 + (lane >> 1);

    // shared weights
    float w2 = W[2], w3 = W[3], w9 = W[9], w10 = W[10];
    // per-channel weights
    float wIn = ch ? W[12] : W[0];
    float wA  = ch ? W[13] : W[1];
    float wE1 = ch ? W[16] : W[4];
    float wE2 = ch ? W[17] : W[5];
    float wI  = ch ? W[18] : W[6];
    float wT  = ch ? W[20] : W[8];
    float wM  = ch ? W[23] : W[11];

    // initial states (v0, u0 = b*v0)
    float vL = -70.f, uL = -14.f, zL = 0.f;   // LLBN
    float vE = -64.f, uE = -16.f;             // EBN
    float vI = -64.f, uI = -16.f;             // IFN
    float vT = -70.f, uT = -14.f, zT = 0.f;   // TN
    float vM = -64.f, uM = -16.f;             // MN

    // software-pipelined S loads (distance 2; g_S is L2-hot after K1)
    float s0 = g_S[b];
    float s1 = g_S[BB + b];

#pragma unroll 1
    for (int t = 0; t < TT; t++) {
        int tf = t + 2; if (tf > TT - 1) tf = TT - 1;
        float s2 = g_S[tf * BB + b];

        float zp = wIn * s0;
        float z2, z3, z4, z5, z6;
        izh(vL, uL, z2, w2 * (zp * wA) + w3 * zL, 0.02f, 0.20f, -65.f, 6.f);
        izh(vE, uE, z3, zp * wE1 + z2 * wE2,      0.02f, 0.25f, -55.f, 0.05f);
        izh(vI, uI, z4, z3 * wI,                  0.02f, 0.25f, -65.f, 6.f);
        izh(vT, uT, z5, w9 * (z3 * wT) + w10 * zT,0.02f, 0.20f, -50.f, 2.f);
        izh(vM, uM, z6, z5 * wM,                  0.02f, 0.25f, -65.f, 6.f);
        zL = z2;
        zT = z5;

        // record layout: f0..3 = z2,z3,z4,z5 | f4..7 = vL,vE,vI,vT |
        //                f8,f9 = z6,vM (ch0) | f10,f11 = z62,vM2 (ch1)
        float* rec = g_R + ((size_t)t * BB + b) * 12;
        if (ch == 0) {
            *(float4*)(rec)     = make_float4(z2, z3, z4, z5);
            *(float4*)(rec + 4) = make_float4(vL, vE, vI, vT);
        }
        *(float2*)(rec + 8 + 2 * ch) = make_float2(z6, vM);

        s0 = s1; s1 = s2;
    }
}

// ---------------------------------------------------------------------------
// K3: t-major scratch -> required [B,T] / [B,T,4] output layout.
// Tile 32 t x 16 b through smem (pad 17 for conflict-free transpose reads).
// Output layout assumption (tuple concatenated flat):
//   [0,BT)    o_spikes   (f8)
//   [BT,2BT)  v          (f9)
//   [2BT,3BT) o_spikes2  (f10)
//   [3BT,4BT) v2         (f11)
//   [4BT,8BT) o_spikes_o [B,T,4] (f0..f3)
//   [8BT,12BT) v_o       [B,T,4] (f4..f7)
// ---------------------------------------------------------------------------
__global__ void __launch_bounds__(256) untranspose_kernel(float* __restrict__ out) {
    __shared__ float tile[12][32][17];
    int tid = threadIdx.x;
    int b0  = blockIdx.x * 16;
    int t0  = blockIdx.y * 32;
    int nt  = TT - t0; if (nt > 32) nt = 32;

    for (int i = tid; i < nt * 16; i += 256) {
        int tl = i >> 4, bl = i & 15;
        const float4* p = (const float4*)(g_R + ((size_t)(t0 + tl) * BB + b0 + bl) * 12);
        float4 r0 = p[0], r1 = p[1], r2 = p[2];
        tile[0][tl][bl] = r0.x;  tile[1][tl][bl] = r0.y;
        tile[2][tl][bl] = r0.z;  tile[3][tl][bl] = r0.w;
        tile[4][tl][bl] = r1.x;  tile[5][tl][bl] = r1.y;
        tile[6][tl][bl] = r1.z;  tile[7][tl][bl] = r1.w;
        tile[8][tl][bl] = r2.x;  tile[9][tl][bl] = r2.y;
        tile[10][tl][bl] = r2.z; tile[11][tl][bl] = r2.w;
    }
    __syncthreads();

    int warp = tid >> 5, lane = tid & 31;

    // scalar planes (f8..f11) -> outputs 0..3, coalesced along t
    for (int row = warp; row < 64; row += 8) {
        int p  = row >> 4;
        int bl = row & 15;
        if (lane < nt)
            out[(size_t)p * BT + (size_t)(b0 + bl) * TT + t0 + lane] = tile[8 + p][lane][bl];
    }
    // interleaved [B,T,4] groups: f0..3 -> +4BT, f4..7 -> +8BT, float4 stores
    for (int row = warp; row < 32; row += 8) {
        int g  = row >> 4;
        int bl = row & 15;
        if (lane < nt) {
            float4 v = make_float4(tile[g * 4 + 0][lane][bl], tile[g * 4 + 1][lane][bl],
                                   tile[g * 4 + 2][lane][bl], tile[g * 4 + 3][lane][bl]);
            ((float4*)(out + (size_t)(4 + 4 * g) * BT))[(size_t)(b0 + bl) * TT + t0 + lane] = v;
        }
    }
}

// ---------------------------------------------------------------------------
extern "C" void kernel_launch(void* const* d_in, const int* in_sizes, int n_in,
                              void* d_out, int out_size) {
    const float* in = (const float*)d_in[0];   // [B, T, 64] float32
    const float* w  = (const float*)d_in[1];   // [24] float32
    float* out = (float*)d_out;

    reduce_kernel<<<dim3(BB / 32, TT), 512>>>(in);
    scan_kernel<<<128, 32>>>(w);
    untranspose_kernel<<<dim3(BB / 16, (TT + 31) / 32), 256>>>(out);
}